// round 8
// baseline (speedup 1.0000x reference)
#include <cuda_runtime.h>
#include <cstdint>

#define BB 64
#define TT 1024
#define KK 256
#define HALF 128
#define SROWS 224          // transT rows cached in backtrace SMEM (224 KB)

// ---------------- scratch ---------------------------------------------------
__device__ float g_state[TT * BB * KK];    // all forward states, 64 MB
__device__ float g_transT[KK * KK];        // transposed transitions

// ---------------- helpers ---------------------------------------------------
__device__ __forceinline__ uint32_t smem_u32(const void* p) {
    return (uint32_t)__cvta_generic_to_shared(p);
}

// monotone float->u32 map: preserves ordering exactly (finite values)
__device__ __forceinline__ unsigned fmono(float f) {
    int b = __float_as_int(f);
    return (unsigned)(b ^ ((b >> 31) | 0x80000000));
}

__device__ __forceinline__ void cluster_sync_all() {
    asm volatile("barrier.cluster.arrive.aligned;" ::: "memory");
    asm volatile("barrier.cluster.wait.aligned;" ::: "memory");
}

__device__ __forceinline__ uint32_t mapa_peer(uint32_t laddr, unsigned peer) {
    uint32_t raddr;
    asm volatile("mapa.shared::cluster.u32 %0, %1, %2;"
                 : "=r"(raddr) : "r"(laddr), "r"(peer));
    return raddr;
}

__device__ __forceinline__ void mbar_init(uint32_t addr, unsigned count) {
    asm volatile("mbarrier.init.shared.b64 [%0], %1;" :: "r"(addr), "r"(count) : "memory");
}
// local arrive(1) + expect 'bytes' of incoming async-store traffic this phase
__device__ __forceinline__ void mbar_arrive_expect_tx(uint32_t addr, unsigned bytes) {
    asm volatile("mbarrier.arrive.expect_tx.shared.b64 _, [%0], %1;"
                 :: "r"(addr), "r"(bytes) : "memory");
}
__device__ __forceinline__ void mbar_wait_cluster(uint32_t addr, unsigned parity) {
    asm volatile(
        "{\n\t"
        ".reg .pred P1;\n\t"
        "WAIT_%=:\n\t"
        "mbarrier.try_wait.parity.acquire.cluster.shared::cta.b64 P1, [%0], %1, 0x989680;\n\t"
        "@P1 bra.uni DONE_%=;\n\t"
        "bra.uni WAIT_%=;\n\t"
        "DONE_%=:\n\t"
        "}"
        :: "r"(addr), "r"(parity) : "memory");
}
// one-way async store to peer SMEM; counts 8 bytes on the peer's mbarrier
__device__ __forceinline__ void st_async_b64(uint32_t raddr, float2 v, uint32_t rmbar) {
    unsigned long long u;
    memcpy(&u, &v, 8);
    asm volatile(
        "st.async.weak.shared::cluster.mbarrier::complete_tx::bytes.b64 [%0], %1, [%2];"
        :: "r"(raddr), "l"(u), "r"(rmbar) : "memory");
}

// bit-exact add: rn(sv*1.0f + tr) == rn(sv + tr); FFMA-imm form runs at rt 1
__device__ __forceinline__ float addx(float sv, float tr) {
    return __fmaf_rn(sv, 1.0f, tr);
}

__global__ void noop_kernel() {}

// ---------------- transpose kernel ------------------------------------------
__global__ void transpose_kernel(const float* __restrict__ trans)
{
    __shared__ float tile[32][33];
    int bx = blockIdx.x, by = blockIdx.y;
    int x = bx * 32 + threadIdx.x;
    #pragma unroll
    for (int r = 0; r < 4; ++r) {
        int y = by * 32 + threadIdx.y + r * 8;
        tile[threadIdx.y + r * 8][threadIdx.x] = trans[y * KK + x];
    }
    __syncthreads();
    int x2 = by * 32 + threadIdx.x;
    #pragma unroll
    for (int r = 0; r < 4; ++r) {
        int y2 = bx * 32 + threadIdx.y + r * 8;
        g_transT[y2 * KK + x2] = tile[threadIdx.x][threadIdx.y + r * 8];
    }
}

// ---------------- forward kernel (G=2 interleaved, st.async exchange) -------
// 2-CTA cluster per batch-pair. CTA rank owns j in [rank*128,+128).
// Warp w, lane = g*4 + q; thread covers j-quad jcol = rank*128+w*16+q*4 and
// i = k*8 + g. Trans in registers, SHARED across both batches.
// Per iteration: A(b0) -> wait(b0) -> B+push(b0) -> A(b1) -> wait(b1) ->
// B+push(b1) -> one syncthreads. Each batch's peer flight is hidden behind
// the other batch's compute.
__global__ void __cluster_dims__(2, 1, 1) __launch_bounds__(256, 1)
fwd_kernel(const float* __restrict__ em, const float* __restrict__ trans)
{
    __shared__ float st[2][2][KK];                     // [buf][batch][K]
    __shared__ __align__(8) unsigned long long mb[2][2]; // [buf][batch]

    const int bid  = blockIdx.x;
    const int cl   = bid >> 1;
    const int b0   = cl * 2;
    const int b1   = b0 + 1;
    const unsigned rank = bid & 1;
    const unsigned peer = rank ^ 1u;
    const int tid  = threadIdx.x;
    const int w    = tid >> 5;
    const int lane = tid & 31;
    const int q    = lane & 3;
    const int g    = lane >> 2;
    const int jcol = rank * HALF + w * 16 + q * 4;

    uint32_t mbl[2][2];
    #pragma unroll
    for (int u = 0; u < 2; ++u)
        #pragma unroll
        for (int v = 0; v < 2; ++v)
            mbl[u][v] = smem_u32(&mb[u][v]);
    if (tid == 0) {
        mbar_init(mbl[0][0], 1); mbar_init(mbl[0][1], 1);
        mbar_init(mbl[1][0], 1); mbar_init(mbl[1][1], 1);
    }

    // transition registers (shared by both batches)
    float4 trA[16], trB[16];
    #pragma unroll
    for (int k = 0; k < 16; ++k)
        trA[k] = *(const float4*)&trans[(rank * HALF + k * 8 + g) * KK + jcol];
    #pragma unroll
    for (int k = 0; k < 16; ++k)
        trB[k] = *(const float4*)&trans[(peer * HALF + k * 8 + g) * KK + jcol];

    // initial state = emissions[b,0,:] for both batches
    {
        float v0 = em[(b0 * TT) * KK + tid];
        float v1 = em[(b1 * TT) * KK + tid];
        st[0][0][tid] = v0;
        st[0][1][tid] = v1;
        if (rank == 0) {
            g_state[b0 * KK + tid] = v0;
            g_state[b1 * KK + tid] = v1;
        }
    }
    __syncthreads();
    cluster_sync_all();          // peer mbar init complete before any st.async

    const bool writer = (lane < 4);
    const int jW = rank * HALF + w * 16 + lane * 4;   // writer's j-quad
    uint32_t pD[2][2], rmb[2][2];
    #pragma unroll
    for (int u = 0; u < 2; ++u) {
        pD[u][0]  = mapa_peer(smem_u32(&st[u][0][jW]), peer);
        pD[u][1]  = mapa_peer(smem_u32(&st[u][1][jW]), peer);
        rmb[u][0] = mapa_peer(mbl[u][0], peer);
        rmb[u][1] = mapa_peer(mbl[u][1], peer);
    }
    unsigned par[2] = {0u, 0u};

    float4 emC0 = make_float4(0.f, 0.f, 0.f, 0.f);
    float4 emC1 = make_float4(0.f, 0.f, 0.f, 0.f);
    if (writer) {
        emC0 = __ldg((const float4*)&em[((b0 * TT + 1) * KK) + jW]);
        emC1 = __ldg((const float4*)&em[((b1 * TT + 1) * KK) + jW]);
    }

    for (int t = 1; t < TT; ++t) {
        const int nb = t & 1;            // buffer being written (state t)
        const int cb = nb ^ 1;           // buffer holding state t-1
        const float* cur0 = st[cb][0];
        const float* cur1 = st[cb][1];

        // announce this phase's incoming bytes for both batches (local, cheap)
        if (tid == 0) {
            mbar_arrive_expect_tx(mbl[nb][0], 512u);
            mbar_arrive_expect_tx(mbl[nb][1], 512u);
        }

        // prefetch next step's emissions
        float4 emN0 = make_float4(0.f, 0.f, 0.f, 0.f);
        float4 emN1 = make_float4(0.f, 0.f, 0.f, 0.f);
        if (writer && (t + 1 < TT)) {
            emN0 = __ldg((const float4*)&em[((b0 * TT + t + 1) * KK) + jW]);
            emN1 = __ldg((const float4*)&em[((b1 * TT + t + 1) * KK) + jW]);
        }

        // ================= batch 0 =================
        float a0, a1, a2, a3;
        {
            float sv = cur0[rank * HALF + g];
            a0 = addx(sv, trA[0].x); a1 = addx(sv, trA[0].y);
            a2 = addx(sv, trA[0].z); a3 = addx(sv, trA[0].w);
        }
        #pragma unroll
        for (int k = 1; k < 16; ++k) {
            float sv = cur0[rank * HALF + k * 8 + g];
            a0 = fmaxf(a0, addx(sv, trA[k].x));
            a1 = fmaxf(a1, addx(sv, trA[k].y));
            a2 = fmaxf(a2, addx(sv, trA[k].z));
            a3 = fmaxf(a3, addx(sv, trA[k].w));
        }
        if (t >= 2)
            mbar_wait_cluster(mbl[cb][0], par[cb]);   // b0 peer bytes (in flight during A)
        #pragma unroll
        for (int k = 0; k < 16; ++k) {
            float sv = cur0[peer * HALF + k * 8 + g];
            a0 = fmaxf(a0, addx(sv, trB[k].x));
            a1 = fmaxf(a1, addx(sv, trB[k].y));
            a2 = fmaxf(a2, addx(sv, trB[k].z));
            a3 = fmaxf(a3, addx(sv, trB[k].w));
        }
        #pragma unroll
        for (int off = 4; off <= 16; off <<= 1) {
            a0 = fmaxf(a0, __shfl_xor_sync(0xffffffffu, a0, off));
            a1 = fmaxf(a1, __shfl_xor_sync(0xffffffffu, a1, off));
            a2 = fmaxf(a2, __shfl_xor_sync(0xffffffffu, a2, off));
            a3 = fmaxf(a3, __shfl_xor_sync(0xffffffffu, a3, off));
        }
        if (writer) {
            float4 ns = make_float4(a0 + emC0.x, a1 + emC0.y,
                                    a2 + emC0.z, a3 + emC0.w);
            *(float4*)&st[nb][0][jW] = ns;
            st_async_b64(pD[nb][0],     make_float2(ns.x, ns.y), rmb[nb][0]);
            st_async_b64(pD[nb][0] + 8, make_float2(ns.z, ns.w), rmb[nb][0]);
            *(float4*)&g_state[(t * BB + b0) * KK + jW] = ns;
        }

        // ================= batch 1 =================
        float c0, c1, c2, c3;
        {
            float sv = cur1[rank * HALF + g];
            c0 = addx(sv, trA[0].x); c1 = addx(sv, trA[0].y);
            c2 = addx(sv, trA[0].z); c3 = addx(sv, trA[0].w);
        }
        #pragma unroll
        for (int k = 1; k < 16; ++k) {
            float sv = cur1[rank * HALF + k * 8 + g];
            c0 = fmaxf(c0, addx(sv, trA[k].x));
            c1 = fmaxf(c1, addx(sv, trA[k].y));
            c2 = fmaxf(c2, addx(sv, trA[k].z));
            c3 = fmaxf(c3, addx(sv, trA[k].w));
        }
        if (t >= 2) {
            mbar_wait_cluster(mbl[cb][1], par[cb]);   // b1 peer bytes
            par[cb] ^= 1u;
        }
        #pragma unroll
        for (int k = 0; k < 16; ++k) {
            float sv = cur1[peer * HALF + k * 8 + g];
            c0 = fmaxf(c0, addx(sv, trB[k].x));
            c1 = fmaxf(c1, addx(sv, trB[k].y));
            c2 = fmaxf(c2, addx(sv, trB[k].z));
            c3 = fmaxf(c3, addx(sv, trB[k].w));
        }
        #pragma unroll
        for (int off = 4; off <= 16; off <<= 1) {
            c0 = fmaxf(c0, __shfl_xor_sync(0xffffffffu, c0, off));
            c1 = fmaxf(c1, __shfl_xor_sync(0xffffffffu, c1, off));
            c2 = fmaxf(c2, __shfl_xor_sync(0xffffffffu, c2, off));
            c3 = fmaxf(c3, __shfl_xor_sync(0xffffffffu, c3, off));
        }
        if (writer) {
            float4 ns = make_float4(c0 + emC1.x, c1 + emC1.y,
                                    c2 + emC1.z, c3 + emC1.w);
            *(float4*)&st[nb][1][jW] = ns;
            st_async_b64(pD[nb][1],     make_float2(ns.x, ns.y), rmb[nb][1]);
            st_async_b64(pD[nb][1] + 8, make_float2(ns.z, ns.w), rmb[nb][1]);
            *(float4*)&g_state[(t * BB + b1) * KK + jW] = ns;
        }

        emC0 = emN0;
        emC1 = emN1;
        __syncthreads();   // local visibility of st[nb][*][own half]
    }

    // drain buf1 (state 1023 peer bytes announced at t=1023, never waited)
    mbar_wait_cluster(mbl[1][0], par[1]);
    mbar_wait_cluster(mbl[1][1], par[1]);
    cluster_sync_all();
}

// ---------------- backtrace: serial argmax recompute along decoded path -----
// One CTA per batch, one active warp. Per step: value-only max tree in lane,
// redux across warp, 8 per-slot ballots, index reconstructed UNIFORMLY in all
// lanes (no shfl on critical path). First-index ties: min(lane*8+slot). Exact.
extern __shared__ float sT[];

__global__ void __launch_bounds__(256, 1) backtrace_kernel(float* __restrict__ out)
{
    const int b   = blockIdx.x;
    const int tid = threadIdx.x;

    for (int idx = tid; idx < SROWS * (KK / 4); idx += 256)
        ((float4*)sT)[idx] = ((const float4*)g_transT)[idx];
    __syncthreads();
    if (tid >= 32) return;
    const int lane = tid;

    // ---- last tag: argmax over state row 1023 ----
    int cur;
    {
        const float4* rp = (const float4*)(g_state + (1023 * BB + b) * KK) + lane * 2;
        float4 sa = __ldg(rp), sb = __ldg(rp + 1);
        unsigned u0 = fmono(sa.x), u1 = fmono(sa.y), u2 = fmono(sa.z), u3 = fmono(sa.w);
        unsigned u4 = fmono(sb.x), u5 = fmono(sb.y), u6 = fmono(sb.z), u7 = fmono(sb.w);
        unsigned um = max(max(max(u0, u1), max(u2, u3)),
                          max(max(u4, u5), max(u6, u7)));
        unsigned gmax = __reduce_max_sync(0xffffffffu, um);
        unsigned m0 = __ballot_sync(0xffffffffu, u0 == gmax);
        unsigned m1 = __ballot_sync(0xffffffffu, u1 == gmax);
        unsigned m2 = __ballot_sync(0xffffffffu, u2 == gmax);
        unsigned m3 = __ballot_sync(0xffffffffu, u3 == gmax);
        unsigned m4 = __ballot_sync(0xffffffffu, u4 == gmax);
        unsigned m5 = __ballot_sync(0xffffffffu, u5 == gmax);
        unsigned m6 = __ballot_sync(0xffffffffu, u6 == gmax);
        unsigned m7 = __ballot_sync(0xffffffffu, u7 == gmax);
        int best = 0x7fffffff, c;
        if (m0) { c = (__ffs(m0) - 1) * 8 + 0; best = c; }
        if (m1) { c = (__ffs(m1) - 1) * 8 + 1; best = c < best ? c : best; }
        if (m2) { c = (__ffs(m2) - 1) * 8 + 2; best = c < best ? c : best; }
        if (m3) { c = (__ffs(m3) - 1) * 8 + 3; best = c < best ? c : best; }
        if (m4) { c = (__ffs(m4) - 1) * 8 + 4; best = c < best ? c : best; }
        if (m5) { c = (__ffs(m5) - 1) * 8 + 5; best = c < best ? c : best; }
        if (m6) { c = (__ffs(m6) - 1) * 8 + 6; best = c < best ? c : best; }
        if (m7) { c = (__ffs(m7) - 1) * 8 + 7; best = c < best ? c : best; }
        cur = best;
        if (lane == 0) out[b * TT + (TT - 1)] = (float)cur;
    }

    // depth-8 register prefetch of state rows (addresses independent of chain)
    float4 pfa[8], pfb[8];
    #pragma unroll
    for (int d = 0; d < 8; ++d) {
        int row = 1022 - d;
        const float4* rp = (const float4*)(g_state + (row * BB + b) * KK) + lane * 2;
        pfa[d] = __ldg(rp);
        pfb[d] = __ldg(rp + 1);
    }

    for (int t = TT - 1; t >= 1; --t) {
        const int slot = (TT - 1 - t) & 7;
        float4 sa = pfa[slot], sb = pfb[slot];

        int nrow = t - 9;
        if (nrow >= 0) {
            const float4* rp = (const float4*)(g_state + (nrow * BB + b) * KK) + lane * 2;
            pfa[slot] = __ldg(rp);
            pfb[slot] = __ldg(rp + 1);
        }

        const float4* trp = (cur < SROWS)
            ? (const float4*)(sT + cur * KK)
            : (const float4*)(g_transT + cur * KK);
        float4 t0 = trp[lane * 2];
        float4 t1 = trp[lane * 2 + 1];

        unsigned u0 = fmono(sa.x + t0.x), u1 = fmono(sa.y + t0.y);
        unsigned u2 = fmono(sa.z + t0.z), u3 = fmono(sa.w + t0.w);
        unsigned u4 = fmono(sb.x + t1.x), u5 = fmono(sb.y + t1.y);
        unsigned u6 = fmono(sb.z + t1.z), u7 = fmono(sb.w + t1.w);
        unsigned um = max(max(max(u0, u1), max(u2, u3)),
                          max(max(u4, u5), max(u6, u7)));
        unsigned gmax = __reduce_max_sync(0xffffffffu, um);
        unsigned m0 = __ballot_sync(0xffffffffu, u0 == gmax);
        unsigned m1 = __ballot_sync(0xffffffffu, u1 == gmax);
        unsigned m2 = __ballot_sync(0xffffffffu, u2 == gmax);
        unsigned m3 = __ballot_sync(0xffffffffu, u3 == gmax);
        unsigned m4 = __ballot_sync(0xffffffffu, u4 == gmax);
        unsigned m5 = __ballot_sync(0xffffffffu, u5 == gmax);
        unsigned m6 = __ballot_sync(0xffffffffu, u6 == gmax);
        unsigned m7 = __ballot_sync(0xffffffffu, u7 == gmax);
        int best = 0x7fffffff, c;
        if (m0) { c = (__ffs(m0) - 1) * 8 + 0; best = c; }
        if (m1) { c = (__ffs(m1) - 1) * 8 + 1; best = c < best ? c : best; }
        if (m2) { c = (__ffs(m2) - 1) * 8 + 2; best = c < best ? c : best; }
        if (m3) { c = (__ffs(m3) - 1) * 8 + 3; best = c < best ? c : best; }
        if (m4) { c = (__ffs(m4) - 1) * 8 + 4; best = c < best ? c : best; }
        if (m5) { c = (__ffs(m5) - 1) * 8 + 5; best = c < best ? c : best; }
        if (m6) { c = (__ffs(m6) - 1) * 8 + 6; best = c < best ? c : best; }
        if (m7) { c = (__ffs(m7) - 1) * 8 + 7; best = c < best ? c : best; }

        if (lane == 0) out[b * TT + (t - 1)] = (float)best;
        cur = best;
    }
}

// ---------------- launch ----------------------------------------------------
extern "C" void kernel_launch(void* const* d_in, const int* in_sizes, int n_in,
                              void* d_out, int out_size)
{
    const float* em    = (const float*)d_in[0];  // [B, T, K] fp32
    const float* trans = (const float*)d_in[1];  // [K, K] fp32
    float* out = (float*)d_out;                  // [B, T] fp32

    const int bt_smem = SROWS * KK * (int)sizeof(float);   // 229376
    cudaFuncSetAttribute(backtrace_kernel,
                         cudaFuncAttributeMaxDynamicSharedMemorySize, bt_smem);

    transpose_kernel<<<dim3(8, 8), dim3(32, 8)>>>(trans);   // launch 1
    noop_kernel<<<1, 32>>>();                               // launch 2
    fwd_kernel<<<BB, 256>>>(em, trans);                     // launch 3 (64 clusters x2 CTA)
    backtrace_kernel<<<BB, 256, bt_smem>>>(out);            // launch 4 <- ncu
    noop_kernel<<<1, 32>>>();                               // launch 5
}

// round 11
// speedup vs baseline: 2.0003x; 2.0003x over previous
#include <cuda_runtime.h>
#include <cstdint>

#define BB 64
#define TT 1024
#define KK 256
#define HALF 128
#define SROWS 224          // transT rows cached in backtrace SMEM (224 KB)

// ---------------- scratch ---------------------------------------------------
__device__ float g_state[TT * BB * KK];    // all forward states, 64 MB
__device__ float g_transT[KK * KK];        // transposed transitions

// ---------------- helpers ---------------------------------------------------
__device__ __forceinline__ uint32_t smem_u32(const void* p) {
    return (uint32_t)__cvta_generic_to_shared(p);
}

// monotone float->u32 map: preserves ordering exactly (finite values)
__device__ __forceinline__ unsigned fmono(float f) {
    int b = __float_as_int(f);
    return (unsigned)(b ^ ((b >> 31) | 0x80000000));
}

__device__ __forceinline__ void cluster_sync_all() {
    asm volatile("barrier.cluster.arrive.aligned;" ::: "memory");
    asm volatile("barrier.cluster.wait.aligned;" ::: "memory");
}

__device__ __forceinline__ uint32_t mapa_peer(uint32_t laddr, unsigned peer) {
    uint32_t raddr;
    asm volatile("mapa.shared::cluster.u32 %0, %1, %2;"
                 : "=r"(raddr) : "r"(laddr), "r"(peer));
    return raddr;
}

__device__ __forceinline__ void mbar_init(uint32_t addr, unsigned count) {
    asm volatile("mbarrier.init.shared.b64 [%0], %1;" :: "r"(addr), "r"(count) : "memory");
}
// local arrive(1) + expect 'bytes' of incoming async-store traffic this phase
__device__ __forceinline__ void mbar_arrive_expect_tx(uint32_t addr, unsigned bytes) {
    asm volatile("mbarrier.arrive.expect_tx.shared.b64 _, [%0], %1;"
                 :: "r"(addr), "r"(bytes) : "memory");
}
__device__ __forceinline__ void mbar_wait_cluster(uint32_t addr, unsigned parity) {
    asm volatile(
        "{\n\t"
        ".reg .pred P1;\n\t"
        "WAIT_%=:\n\t"
        "mbarrier.try_wait.parity.acquire.cluster.shared::cta.b64 P1, [%0], %1, 0x989680;\n\t"
        "@P1 bra.uni DONE_%=;\n\t"
        "bra.uni WAIT_%=;\n\t"
        "DONE_%=:\n\t"
        "}"
        :: "r"(addr), "r"(parity) : "memory");
}
// one-way async store to peer SMEM; counts 8 bytes on the peer's mbarrier
__device__ __forceinline__ void st_async_b64(uint32_t raddr, float2 v, uint32_t rmbar) {
    unsigned long long u;
    memcpy(&u, &v, 8);
    asm volatile(
        "st.async.weak.shared::cluster.mbarrier::complete_tx::bytes.b64 [%0], %1, [%2];"
        :: "r"(raddr), "l"(u), "r"(rmbar) : "memory");
}

// bit-exact add: rn(sv*1.0f + tr) == rn(sv + tr); FFMA-imm form runs at rt 1
__device__ __forceinline__ float addx(float sv, float tr) {
    return __fmaf_rn(sv, 1.0f, tr);
}

__global__ void noop_kernel() {}

// ---------------- transpose kernel ------------------------------------------
__global__ void transpose_kernel(const float* __restrict__ trans)
{
    __shared__ float tile[32][33];
    int bx = blockIdx.x, by = blockIdx.y;
    int x = bx * 32 + threadIdx.x;
    #pragma unroll
    for (int r = 0; r < 4; ++r) {
        int y = by * 32 + threadIdx.y + r * 8;
        tile[threadIdx.y + r * 8][threadIdx.x] = trans[y * KK + x];
    }
    __syncthreads();
    int x2 = by * 32 + threadIdx.x;
    #pragma unroll
    for (int r = 0; r < 4; ++r) {
        int y2 = bx * 32 + threadIdx.y + r * 8;
        g_transT[y2 * KK + x2] = tile[threadIdx.x][threadIdx.y + r * 8];
    }
}

// ---------------- forward kernel (R6 verbatim: st.async exchange) -----------
// 2-CTA cluster per batch. CTA rank owns j in [rank*128,+128).
// Warp w, lane = g*4 + q; thread covers j-quad jcol = rank*128+w*16+q*4 and
// i = k*8 + g. Trans in registers. Peer half exchanged via st.async with
// transaction-counting mbarriers: NO release fence, NO store drain at BAR.
__global__ void __cluster_dims__(2, 1, 1) __launch_bounds__(256, 1)
fwd_kernel(const float* __restrict__ em, const float* __restrict__ trans)
{
    __shared__ float st[2][KK];
    __shared__ __align__(8) unsigned long long mb[2];

    const int bid  = blockIdx.x;
    const int b    = bid >> 1;
    const unsigned rank = bid & 1;
    const unsigned peer = rank ^ 1u;
    const int tid  = threadIdx.x;
    const int w    = tid >> 5;
    const int lane = tid & 31;
    const int q    = lane & 3;
    const int g    = lane >> 2;
    const int jcol = rank * HALF + w * 16 + q * 4;

    const uint32_t mb0_l = smem_u32(&mb[0]);
    const uint32_t mb1_l = mb0_l + 8;
    if (tid == 0) { mbar_init(mb0_l, 1); mbar_init(mb1_l, 1); }

    // transition registers
    float4 trA[16], trB[16];
    #pragma unroll
    for (int k = 0; k < 16; ++k)
        trA[k] = *(const float4*)&trans[(rank * HALF + k * 8 + g) * KK + jcol];
    #pragma unroll
    for (int k = 0; k < 16; ++k)
        trB[k] = *(const float4*)&trans[(peer * HALF + k * 8 + g) * KK + jcol];

    // initial state = emissions[b,0,:] (both CTAs load full row locally)
    {
        float v = em[(b * TT) * KK + tid];
        st[0][tid] = v;
        if (rank == 0) g_state[b * KK + tid] = v;
    }
    __syncthreads();
    cluster_sync_all();          // peer mbar init complete before any st.async

    const bool writer = (lane < 4);
    const int jW = rank * HALF + w * 16 + lane * 4;   // writer's j-quad
    const uint32_t pA0 = mapa_peer(smem_u32(&st[0][jW]), peer);
    const uint32_t pA1 = mapa_peer(smem_u32(&st[1][jW]), peer);
    const uint32_t rmb0 = mapa_peer(mb0_l, peer);
    const uint32_t rmb1 = mapa_peer(mb1_l, peer);
    unsigned p0 = 0, p1 = 0;

    float4 emCur = make_float4(0.f, 0.f, 0.f, 0.f);
    if (writer)
        emCur = __ldg((const float4*)&em[((b * TT + 1) * KK) + jW]);

    for (int t = 1; t < TT; ++t) {
        const int nb = t & 1;            // buffer being written (state t)
        const float* cur = st[nb ^ 1];
        float*       nxt = st[nb];

        // announce this phase's expected incoming bytes (local, cheap).
        if (tid == 0)
            mbar_arrive_expect_tx(nb ? mb1_l : mb0_l, 512u);

        // prefetch next step's emission
        float4 emNxt = make_float4(0.f, 0.f, 0.f, 0.f);
        if (writer && (t + 1 < TT))
            emNxt = __ldg((const float4*)&em[((b * TT + t + 1) * KK) + jW]);

        // ---- phase A: own-half i (locally produced, no wait) ----
        float a0, a1, a2, a3;
        {
            float sv = cur[rank * HALF + g];
            a0 = addx(sv, trA[0].x); a1 = addx(sv, trA[0].y);
            a2 = addx(sv, trA[0].z); a3 = addx(sv, trA[0].w);
        }
        #pragma unroll
        for (int k = 1; k < 16; ++k) {
            float sv = cur[rank * HALF + k * 8 + g];
            a0 = fmaxf(a0, addx(sv, trA[k].x));
            a1 = fmaxf(a1, addx(sv, trA[k].y));
            a2 = fmaxf(a2, addx(sv, trA[k].z));
            a3 = fmaxf(a3, addx(sv, trA[k].w));
        }

        // ---- wait for peer half of state(t-1): tx-complete mbar ----
        if (t >= 2) {
            if (nb) { mbar_wait_cluster(mb0_l, p0); p0 ^= 1u; }   // cur buf = 0
            else    { mbar_wait_cluster(mb1_l, p1); p1 ^= 1u; }   // cur buf = 1
        }

        // ---- phase B: peer-half i ----
        #pragma unroll
        for (int k = 0; k < 16; ++k) {
            float sv = cur[peer * HALF + k * 8 + g];
            a0 = fmaxf(a0, addx(sv, trB[k].x));
            a1 = fmaxf(a1, addx(sv, trB[k].y));
            a2 = fmaxf(a2, addx(sv, trB[k].z));
            a3 = fmaxf(a3, addx(sv, trB[k].w));
        }

        // butterfly max over the 8 i-groups (lane bits 2..4)
        #pragma unroll
        for (int off = 4; off <= 16; off <<= 1) {
            a0 = fmaxf(a0, __shfl_xor_sync(0xffffffffu, a0, off));
            a1 = fmaxf(a1, __shfl_xor_sync(0xffffffffu, a1, off));
            a2 = fmaxf(a2, __shfl_xor_sync(0xffffffffu, a2, off));
            a3 = fmaxf(a3, __shfl_xor_sync(0xffffffffu, a3, off));
        }

        if (writer) {
            float4 ns = make_float4(a0 + emCur.x, a1 + emCur.y,
                                    a2 + emCur.z, a3 + emCur.w);
            *(float4*)&nxt[jW] = ns;                            // local copy
            uint32_t pD = nb ? pA1 : pA0;                       // peer copy
            uint32_t pM = nb ? rmb1 : rmb0;
            st_async_b64(pD,     make_float2(ns.x, ns.y), pM);  // 8B tx each
            st_async_b64(pD + 8, make_float2(ns.z, ns.w), pM);
            *(float4*)&g_state[(t * BB + b) * KK + jW] = ns;    // for backtrace
        }
        emCur = emNxt;

        __syncthreads();   // local visibility of nxt[own half] for next phase A
    }

    // drain: consume the final phase of buffer 1 so no st.async targets our
    // SMEM after exit.
    mbar_wait_cluster(mb1_l, p1);
    cluster_sync_all();
}

// ---------------- backtrace: serial argmax recompute along decoded path -----
// One CTA per batch, one active warp. Chain loop UNROLLED x8 so the prefetch
// buffers are static registers (no local-memory spill). Per step exactly TWO
// warp collectives: redux.max (value) + redux.min (first index). Exact
// first-index tie-break: min over candidates lane*8+slot with u == gmax.
extern __shared__ float sT[];

__global__ void __launch_bounds__(256, 1) backtrace_kernel(float* __restrict__ out)
{
    const int b   = blockIdx.x;
    const int tid = threadIdx.x;

    for (int idx = tid; idx < SROWS * (KK / 4); idx += 256)
        ((float4*)sT)[idx] = ((const float4*)g_transT)[idx];
    __syncthreads();
    if (tid >= 32) return;
    const int lane = tid;
    const int base = lane * 8;
    const unsigned FULL = 0xffffffffu;
    const int BIG = 0x7fffffff;

    int cur;

    // ---- last tag: argmax over state row 1023 ----
    {
        const float4* rp = (const float4*)(g_state + (1023 * BB + b) * KK) + lane * 2;
        float4 sa = __ldg(rp), sb = __ldg(rp + 1);
        unsigned u0 = fmono(sa.x), u1 = fmono(sa.y), u2 = fmono(sa.z), u3 = fmono(sa.w);
        unsigned u4 = fmono(sb.x), u5 = fmono(sb.y), u6 = fmono(sb.z), u7 = fmono(sb.w);
        unsigned um = max(max(max(u0, u1), max(u2, u3)),
                          max(max(u4, u5), max(u6, u7)));
        unsigned gmax = __reduce_max_sync(FULL, um);
        int i0 = (u0 == gmax) ? base + 0 : BIG;
        int i1 = (u1 == gmax) ? base + 1 : BIG;
        int i2 = (u2 == gmax) ? base + 2 : BIG;
        int i3 = (u3 == gmax) ? base + 3 : BIG;
        int i4 = (u4 == gmax) ? base + 4 : BIG;
        int i5 = (u5 == gmax) ? base + 5 : BIG;
        int i6 = (u6 == gmax) ? base + 6 : BIG;
        int i7 = (u7 == gmax) ? base + 7 : BIG;
        int idx = min(min(min(i0, i1), min(i2, i3)),
                      min(min(i4, i5), min(i6, i7)));
        cur = __reduce_min_sync(FULL, idx);
        if (lane == 0) out[b * TT + (TT - 1)] = (float)cur;
    }

    // one chain step: state row (t-1) given in (sa, sb); updates cur, writes out
    auto argstep = [&](float4 sa, float4 sb, int t) {
        const float* trow = (cur < SROWS) ? (sT + cur * KK)
                                          : (g_transT + cur * KK);
        float4 t0 = *(const float4*)(trow + base);
        float4 t1 = *(const float4*)(trow + base + 4);
        unsigned u0 = fmono(sa.x + t0.x), u1 = fmono(sa.y + t0.y);
        unsigned u2 = fmono(sa.z + t0.z), u3 = fmono(sa.w + t0.w);
        unsigned u4 = fmono(sb.x + t1.x), u5 = fmono(sb.y + t1.y);
        unsigned u6 = fmono(sb.z + t1.z), u7 = fmono(sb.w + t1.w);
        unsigned um = max(max(max(u0, u1), max(u2, u3)),
                          max(max(u4, u5), max(u6, u7)));
        unsigned gmax = __reduce_max_sync(FULL, um);
        int i0 = (u0 == gmax) ? base + 0 : BIG;
        int i1 = (u1 == gmax) ? base + 1 : BIG;
        int i2 = (u2 == gmax) ? base + 2 : BIG;
        int i3 = (u3 == gmax) ? base + 3 : BIG;
        int i4 = (u4 == gmax) ? base + 4 : BIG;
        int i5 = (u5 == gmax) ? base + 5 : BIG;
        int i6 = (u6 == gmax) ? base + 6 : BIG;
        int i7 = (u7 == gmax) ? base + 7 : BIG;
        int idx = min(min(min(i0, i1), min(i2, i3)),
                      min(min(i4, i5), min(i6, i7)));
        cur = __reduce_min_sync(FULL, idx);
        if (lane == 0) out[b * TT + (t - 1)] = (float)cur;
    };

    // depth-8 register prefetch; slot d holds row (1022 - d) = (t-1) at t=1023-d
    float4 pfa[8], pfb[8];
    #pragma unroll
    for (int d = 0; d < 8; ++d) {
        const float4* rp = (const float4*)(g_state + ((1022 - d) * BB + b) * KK) + lane * 2;
        pfa[d] = __ldg(rp);
        pfb[d] = __ldg(rp + 1);
    }

    int t = 1023;
    while (t >= 8) {                 // full blocks: slots are compile-time
        #pragma unroll
        for (int uu = 0; uu < 8; ++uu) {
            float4 sa = pfa[uu], sb = pfb[uu];
            int nrow = t - 9;        // refill slot uu for use 8 iters from now
            if (nrow >= 0) {
                const float4* rp = (const float4*)(g_state + (nrow * BB + b) * KK) + lane * 2;
                pfa[uu] = __ldg(rp);
                pfb[uu] = __ldg(rp + 1);
            }
            argstep(sa, sb, t);
            --t;
        }
    }
    while (t >= 1) {                 // tail (<=7 iters): direct loads, no arrays
        const float4* rp = (const float4*)(g_state + ((t - 1) * BB + b) * KK) + lane * 2;
        float4 sa = __ldg(rp), sb = __ldg(rp + 1);
        argstep(sa, sb, t);
        --t;
    }
}

// ---------------- launch ----------------------------------------------------
extern "C" void kernel_launch(void* const* d_in, const int* in_sizes, int n_in,
                              void* d_out, int out_size)
{
    const float* em    = (const float*)d_in[0];  // [B, T, K] fp32
    const float* trans = (const float*)d_in[1];  // [K, K] fp32
    float* out = (float*)d_out;                  // [B, T] fp32

    const int bt_smem = SROWS * KK * (int)sizeof(float);   // 229376
    cudaFuncSetAttribute(backtrace_kernel,
                         cudaFuncAttributeMaxDynamicSharedMemorySize, bt_smem);

    transpose_kernel<<<dim3(8, 8), dim3(32, 8)>>>(trans);   // launch 1
    noop_kernel<<<1, 32>>>();                               // launch 2
    fwd_kernel<<<2 * BB, 256>>>(em, trans);                 // launch 3
    backtrace_kernel<<<BB, 256, bt_smem>>>(out);            // launch 4 <- ncu
    noop_kernel<<<1, 32>>>();                               // launch 5
}